// round 1
// baseline (speedup 1.0000x reference)
#include <cuda_runtime.h>
#include <cuda_bf16.h>
#include <cstdint>

// Problem constants (from reference)
constexpr int NUM_TOKENS   = 32768;
constexpr int NUM_BLOCKS   = 1024;
constexpr int BLOCK_SIZE   = 128;
constexpr int NUM_KV_HEADS = 8;
constexpr int HEAD_DIM     = 128;
constexpr int TOKEN_ELEMS  = NUM_KV_HEADS * HEAD_DIM;            // 1024 floats / slot
constexpr int NUM_SLOTS    = NUM_BLOCKS * BLOCK_SIZE;            // 131072
constexpr long long TOTAL_ELEMS = (long long)NUM_SLOTS * TOKEN_ELEMS; // 134217728
constexpr long long TOTAL_VEC4  = TOTAL_ELEMS / 4;               // 33554432 float4
constexpr float FP8_MAX = 240.0f;

// Scratch: inverse map slot -> token index (-1 if no token writes this slot)
__device__ int g_slot_to_token[NUM_SLOTS];

__global__ void fill_map_kernel() {
    int i = blockIdx.x * blockDim.x + threadIdx.x;
    if (i < NUM_SLOTS) g_slot_to_token[i] = -1;
}

__global__ void scatter_map_kernel(const int* __restrict__ block_indices,
                                   const int* __restrict__ block_offset) {
    int t = blockIdx.x * blockDim.x + threadIdx.x;
    if (t < NUM_TOKENS) {
        int slot = block_indices[t] * BLOCK_SIZE + block_offset[t];
        g_slot_to_token[slot] = t;
    }
}

__global__ void __launch_bounds__(256)
fused_kvcache_kernel(const float4* __restrict__ input,
                     const float4* __restrict__ cache,
                     const float*  __restrict__ scale_input,
                     const float*  __restrict__ scale_output,
                     float4* __restrict__ out) {
    const float si  = __ldg(scale_input);
    const float so  = __ldg(scale_output);
    const float rsi = 1.0f / si;

    const long long stride = (long long)gridDim.x * blockDim.x;
    for (long long i = (long long)blockIdx.x * blockDim.x + threadIdx.x;
         i < TOTAL_VEC4; i += stride) {
        // 256 float4 per slot -> slot id uniform across each warp
        int slot = (int)(i >> 8);
        int tok  = g_slot_to_token[slot];
        float4 v;
        if (tok >= 0) {
            // quantize (clip) then dequant-scale the incoming token
            v = __ldg(&input[(long long)tok * (TOKEN_ELEMS / 4) + (int)(i & 255)]);
            v.x = fminf(fmaxf(v.x * rsi, -FP8_MAX), FP8_MAX) * so;
            v.y = fminf(fmaxf(v.y * rsi, -FP8_MAX), FP8_MAX) * so;
            v.z = fminf(fmaxf(v.z * rsi, -FP8_MAX), FP8_MAX) * so;
            v.w = fminf(fmaxf(v.w * rsi, -FP8_MAX), FP8_MAX) * so;
        } else {
            v = __ldg(&cache[i]);
            v.x *= so; v.y *= so; v.z *= so; v.w *= so;
        }
        out[i] = v;
    }
}

extern "C" void kernel_launch(void* const* d_in, const int* in_sizes, int n_in,
                              void* d_out, int out_size) {
    const float4* input         = (const float4*)d_in[0];
    const float4* cache         = (const float4*)d_in[1];
    const int*    block_indices = (const int*)d_in[2];
    const int*    block_offset  = (const int*)d_in[3];
    const float*  scale_input   = (const float*)d_in[4];
    const float*  scale_output  = (const float*)d_in[5];
    float4*       out           = (float4*)d_out;

    fill_map_kernel<<<(NUM_SLOTS + 255) / 256, 256>>>();
    scatter_map_kernel<<<(NUM_TOKENS + 255) / 256, 256>>>(block_indices, block_offset);

    // ~33.5M float4 units; give each thread ~8 iterations for MLP
    const int threads = 256;
    const int blocks  = 16384;
    fused_kvcache_kernel<<<blocks, threads>>>(input, cache, scale_input, scale_output, out);
}